// round 5
// baseline (speedup 1.0000x reference)
#include <cuda_runtime.h>
#include <math.h>

#define BOUND        1.0f
#define MIN_NEAR     0.2f
#define T_THRESH     1e-4f
#define BG_COLOR     1.0f
#define N_STEPS      128

// 4 rays per warp, 8 lanes per ray. Lane (g=lane>>3, sl=lane&7) owns samples
// sl*16 .. sl*16+15 of ray 4w+g. Each shuffle instruction (scan + reduction)
// serves all 4 rays; slab test computed per-lane for its own ray.
// Phase 1: load sigma, compute v_i = exp(-sigma*delta) (+eps), total product.
// Phase 2: 3-stage segment scan -> exclusive prefix; sequential running-T
// weight loop over 16 samples with rgb chunk double-buffering.
__global__ __launch_bounds__(256)
void nerf_composite_kernel(const float* __restrict__ rays_o,
                           const float* __restrict__ rays_d,
                           const float* __restrict__ sigmas,
                           const float* __restrict__ rgbs,
                           float* __restrict__ out,
                           int N)
{
    const unsigned FULL = 0xFFFFFFFFu;
    int w = (blockIdx.x * blockDim.x + threadIdx.x) >> 5;
    int lane = threadIdx.x & 31;
    int g  = lane >> 3;     // ray slot within warp
    int sl = lane & 7;      // lane within ray segment

    long long rbase = 4LL * w;
    if (rbase >= N) return;
    long long r = rbase + g;
    if (r >= N) r = N - 1;             // clamp (duplicate writes are identical)

    // ---- issue loads early: 4 sigma float4 + rgb chunk0 (3 float4) ----
    const float4* sig4 = (const float4*)(sigmas + r * N_STEPS);
    const float4* rgb4 = (const float4*)(rgbs   + r * (N_STEPS * 3));
    const int sb = sl * 4;     // sigma float4 base
    const int cb = sl * 12;    // rgb float4 base

    float4 s0 = sig4[sb + 0];
    float4 s1 = sig4[sb + 1];
    float4 s2 = sig4[sb + 2];
    float4 s3 = sig4[sb + 3];
    float4 p0 = rgb4[cb + 0];
    float4 p1 = rgb4[cb + 1];
    float4 p2 = rgb4[cb + 2];

    // ---- slab test (each lane: its own ray) ----
    float ox = rays_o[3 * r + 0], oy = rays_o[3 * r + 1], oz = rays_o[3 * r + 2];
    float dx = rays_d[3 * r + 0], dy = rays_d[3 * r + 1], dz = rays_d[3 * r + 2];
    if (fabsf(dx) < 1e-8f) dx = 1e-8f;
    if (fabsf(dy) < 1e-8f) dy = 1e-8f;
    if (fabsf(dz) < 1e-8f) dz = 1e-8f;
    float ix = 1.0f / dx, iy = 1.0f / dy, iz = 1.0f / dz;
    float t1x = (-BOUND - ox) * ix, t2x = (BOUND - ox) * ix;
    float t1y = (-BOUND - oy) * iy, t2y = (BOUND - oy) * iy;
    float t1z = (-BOUND - oz) * iz, t2z = (BOUND - oz) * iz;
    float nearv = fmaxf(fmaxf(fminf(t1x, t2x), fminf(t1y, t2y)), fminf(t1z, t2z));
    float farv  = fminf(fminf(fmaxf(t1x, t2x), fmaxf(t1y, t2y)), fmaxf(t1z, t2z));
    nearv = fmaxf(nearv, MIN_NEAR);
    farv  = fmaxf(farv, nearv + 1e-4f);
    const float delta = (farv - nearv) * (1.0f / (float)N_STEPS);
    const float nd = -delta;

    // ---- survival values v_i = exp(-sigma_i*delta) + 1e-10 ----
    float v[16];
    v[ 0] = __expf(s0.x * nd) + 1e-10f;
    v[ 1] = __expf(s0.y * nd) + 1e-10f;
    v[ 2] = __expf(s0.z * nd) + 1e-10f;
    v[ 3] = __expf(s0.w * nd) + 1e-10f;
    v[ 4] = __expf(s1.x * nd) + 1e-10f;
    v[ 5] = __expf(s1.y * nd) + 1e-10f;
    v[ 6] = __expf(s1.z * nd) + 1e-10f;
    v[ 7] = __expf(s1.w * nd) + 1e-10f;
    v[ 8] = __expf(s2.x * nd) + 1e-10f;
    v[ 9] = __expf(s2.y * nd) + 1e-10f;
    v[10] = __expf(s2.z * nd) + 1e-10f;
    v[11] = __expf(s2.w * nd) + 1e-10f;
    v[12] = __expf(s3.x * nd) + 1e-10f;
    v[13] = __expf(s3.y * nd) + 1e-10f;
    v[14] = __expf(s3.z * nd) + 1e-10f;
    v[15] = __expf(s3.w * nd) + 1e-10f;

    // total product (tree for ILP)
    float m0 = (v[0] * v[1]) * (v[2] * v[3]);
    float m1 = (v[4] * v[5]) * (v[6] * v[7]);
    float m2 = (v[8] * v[9]) * (v[10] * v[11]);
    float m3 = (v[12] * v[13]) * (v[14] * v[15]);
    float tot = (m0 * m1) * (m2 * m3);

    // ---- 3-stage inclusive scan-product within 8-lane segments ----
    float p = tot;
    {
        float q = __shfl_up_sync(FULL, p, 1);  if (sl >= 1) p *= q;
        q       = __shfl_up_sync(FULL, p, 2);  if (sl >= 2) p *= q;
        q       = __shfl_up_sync(FULL, p, 4);  if (sl >= 4) p *= q;
    }
    float excl = __shfl_up_sync(FULL, p, 1);
    if (sl == 0) excl = 1.0f;

    // ---- phase 2: running-T weight loop, rgb double-buffered ----
    float T = excl;
    float wsum = 0.0f, wt = 0.0f, wr = 0.0f, wgc = 0.0f, wb = 0.0f;
    const float tbase = nearv + ((float)(sl * 16) + 0.5f) * delta;

    float4 n0, n1, n2;   // next chunk buffers

#define DO_SAMPLE(I, R, G, B)                                            \
    {                                                                    \
        float vv = v[I];                                                 \
        float ww = (T > T_THRESH) ? (1.0f - vv) * T : 0.0f;              \
        float tv = fmaf((float)(I), delta, tbase);                       \
        wsum += ww;                                                      \
        wt    = fmaf(ww, tv, wt);                                        \
        wr    = fmaf(ww, (R), wr);                                       \
        wgc   = fmaf(ww, (G), wgc);                                      \
        wb    = fmaf(ww, (B), wb);                                       \
        T *= vv;                                                         \
    }

    // chunk 0 (samples 0-3), prefetch chunk 1
    n0 = rgb4[cb + 3]; n1 = rgb4[cb + 4]; n2 = rgb4[cb + 5];
    DO_SAMPLE(0, p0.x, p0.y, p0.z)
    DO_SAMPLE(1, p0.w, p1.x, p1.y)
    DO_SAMPLE(2, p1.z, p1.w, p2.x)
    DO_SAMPLE(3, p2.y, p2.z, p2.w)

    // chunk 1 (samples 4-7), prefetch chunk 2
    p0 = rgb4[cb + 6]; p1 = rgb4[cb + 7]; p2 = rgb4[cb + 8];
    DO_SAMPLE(4, n0.x, n0.y, n0.z)
    DO_SAMPLE(5, n0.w, n1.x, n1.y)
    DO_SAMPLE(6, n1.z, n1.w, n2.x)
    DO_SAMPLE(7, n2.y, n2.z, n2.w)

    // chunk 2 (samples 8-11), prefetch chunk 3
    n0 = rgb4[cb + 9]; n1 = rgb4[cb + 10]; n2 = rgb4[cb + 11];
    DO_SAMPLE(8,  p0.x, p0.y, p0.z)
    DO_SAMPLE(9,  p0.w, p1.x, p1.y)
    DO_SAMPLE(10, p1.z, p1.w, p2.x)
    DO_SAMPLE(11, p2.y, p2.z, p2.w)

    // chunk 3 (samples 12-15)
    DO_SAMPLE(12, n0.x, n0.y, n0.z)
    DO_SAMPLE(13, n0.w, n1.x, n1.y)
    DO_SAMPLE(14, n1.z, n1.w, n2.x)
    DO_SAMPLE(15, n2.y, n2.z, n2.w)
#undef DO_SAMPLE

    // ---- 3-stage butterfly reduction within 8-lane segments (5 values) ----
    #pragma unroll
    for (int off = 4; off > 0; off >>= 1) {
        wsum += __shfl_xor_sync(FULL, wsum, off);
        wt   += __shfl_xor_sync(FULL, wt,   off);
        wr   += __shfl_xor_sync(FULL, wr,   off);
        wgc  += __shfl_xor_sync(FULL, wgc,  off);
        wb   += __shfl_xor_sync(FULL, wb,   off);
    }

    // ---- writes: lanes sl=0..4 each store one output (all hold the sums) ----
    float bg = (1.0f - wsum) * BG_COLOR;
    float* img   = out;
    float* depth = out + (size_t)3 * N;
    float* dnorm = out + (size_t)4 * N;

    if (sl == 0)      img[3 * r + 0] = wr  + bg;
    else if (sl == 1) img[3 * r + 1] = wgc + bg;
    else if (sl == 2) img[3 * r + 2] = wb  + bg;
    else if (sl == 3) depth[r] = wt;
    else if (sl == 4) dnorm[r] = fmaxf(wt - nearv, 0.0f) / (farv - nearv);
}

extern "C" void kernel_launch(void* const* d_in, const int* in_sizes, int n_in,
                              void* d_out, int out_size)
{
    const float* rays_o = (const float*)d_in[0];
    const float* rays_d = (const float*)d_in[1];
    const float* sigmas = (const float*)d_in[2];
    const float* rgbs   = (const float*)d_in[3];
    float* out = (float*)d_out;

    int N = in_sizes[0] / 3;   // rays_o is [N,3]

    // 4 rays per warp, 8 warps per block -> 32 rays per block
    int rays_per_block = 32;
    int blocks = (N + rays_per_block - 1) / rays_per_block;
    nerf_composite_kernel<<<blocks, 256>>>(rays_o, rays_d, sigmas, rgbs, out, N);
}

// round 6
// speedup vs baseline: 1.1587x; 1.1587x over previous
#include <cuda_runtime.h>
#include <math.h>

#define BOUND        1.0f
#define MIN_NEAR     0.2f
#define T_THRESH     1e-4f
#define BG_COLOR     1.0f
#define N_STEPS      128

// One warp per ray. Lane l owns samples 4l..4l+3 (lane-contiguous float4
// addresses -> 512B coalesced per LDG.128 warp instruction; this access
// pattern is load-bearing, R5 proved the alternatives explode L1).
// Reduction: 3 butterfly stages to 4 cosets + tiny smem combine; weights in
// difference form w_i = T_i - T_{i+1}.
__global__ __launch_bounds__(256)
void nerf_composite_kernel(const float* __restrict__ rays_o,
                           const float* __restrict__ rays_d,
                           const float* __restrict__ sigmas,
                           const float* __restrict__ rgbs,
                           float* __restrict__ out,
                           int N)
{
    const unsigned FULL = 0xFFFFFFFFu;
    __shared__ float red[8][4][6];   // [warp][coset][5 partials + pad]

    int wib  = threadIdx.x >> 5;
    int w    = (blockIdx.x * blockDim.x + threadIdx.x) >> 5;
    int lane = threadIdx.x & 31;
    if (w >= N) return;
    const int r = w;

    // ---- 4 coalesced LDG.128 per lane ----
    const float4* sig4 = (const float4*)(sigmas + (size_t)r * N_STEPS);
    const float4* rgb4 = (const float4*)(rgbs   + (size_t)r * (N_STEPS * 3));

    float4 s4 = sig4[lane];
    float4 c0 = rgb4[3 * lane + 0];
    float4 c1 = rgb4[3 * lane + 1];
    float4 c2 = rgb4[3 * lane + 2];
    // sample 0: (c0.x c0.y c0.z)  sample 1: (c0.w c1.x c1.y)
    // sample 2: (c1.z c1.w c2.x)  sample 3: (c2.y c2.z c2.w)

    // ---- slab test (overlaps the loads) ----
    float ox = rays_o[3 * r + 0], oy = rays_o[3 * r + 1], oz = rays_o[3 * r + 2];
    float dx = rays_d[3 * r + 0], dy = rays_d[3 * r + 1], dz = rays_d[3 * r + 2];
    if (fabsf(dx) < 1e-8f) dx = 1e-8f;
    if (fabsf(dy) < 1e-8f) dy = 1e-8f;
    if (fabsf(dz) < 1e-8f) dz = 1e-8f;

    float ix = 1.0f / dx, iy = 1.0f / dy, iz = 1.0f / dz;
    float t1x = (-BOUND - ox) * ix, t2x = (BOUND - ox) * ix;
    float t1y = (-BOUND - oy) * iy, t2y = (BOUND - oy) * iy;
    float t1z = (-BOUND - oz) * iz, t2z = (BOUND - oz) * iz;

    float nearv = fmaxf(fmaxf(fminf(t1x, t2x), fminf(t1y, t2y)), fminf(t1z, t2z));
    float farv  = fminf(fminf(fmaxf(t1x, t2x), fmaxf(t1y, t2y)), fmaxf(t1z, t2z));
    nearv = fmaxf(nearv, MIN_NEAR);
    farv  = fmaxf(farv, nearv + 1e-4f);

    const float delta = (farv - nearv) * (1.0f / (float)N_STEPS);
    const float nd = -delta;

    // ---- survival values (eps kept to match reference cumprod) ----
    float v0 = __expf(s4.x * nd) + 1e-10f;
    float v1 = __expf(s4.y * nd) + 1e-10f;
    float v2 = __expf(s4.z * nd) + 1e-10f;
    float v3 = __expf(s4.w * nd) + 1e-10f;

    // lane-local prefix products
    float lp1 = v0;
    float lp2 = v0 * v1;
    float lp3 = lp2 * v2;
    float tot = lp3 * v3;

    // warp inclusive scan-product over lane totals
    float p = tot;
    #pragma unroll
    for (int off = 1; off < 32; off <<= 1) {
        float q = __shfl_up_sync(FULL, p, off);
        if (lane >= off) p *= q;
    }
    float excl = __shfl_up_sync(FULL, p, 1);
    if (lane == 0) excl = 1.0f;

    // exclusive transmittance per sample; weights in difference form:
    // alpha_i*T_i = T_i - T_{i+1} + 1e-10*T_i  (last term negligible)
    float T0 = excl;
    float T1 = excl * lp1;
    float T2 = excl * lp2;
    float T3 = excl * lp3;
    float T4 = excl * tot;

    float w0 = (T0 > T_THRESH) ? (T0 - T1) : 0.0f;
    float w1 = (T1 > T_THRESH) ? (T1 - T2) : 0.0f;
    float w2 = (T2 > T_THRESH) ? (T2 - T3) : 0.0f;
    float w3 = (T3 > T_THRESH) ? (T3 - T4) : 0.0f;

    // ---- accumulate (depth factored: wt = tbase*wsum + delta*(w1+2w2+3w3)) ----
    float wsum = (w0 + w1) + (w2 + w3);
    float k = fmaf(2.0f, w2, w1);
    k = fmaf(3.0f, w3, k);
    float tbase = fmaf((float)(4 * lane) + 0.5f, delta, nearv);
    float wt = fmaf(delta, k, tbase * wsum);

    float wr = w0 * c0.x; wr = fmaf(w1, c0.w, wr); wr = fmaf(w2, c1.z, wr); wr = fmaf(w3, c2.y, wr);
    float wg = w0 * c0.y; wg = fmaf(w1, c1.x, wg); wg = fmaf(w2, c1.w, wg); wg = fmaf(w3, c2.z, wg);
    float wb = w0 * c0.z; wb = fmaf(w1, c1.y, wb); wb = fmaf(w2, c2.x, wb); wb = fmaf(w3, c2.w, wb);

    // ---- 3 butterfly stages -> 4 cosets (keyed by lane&3) ----
    #pragma unroll
    for (int off = 16; off >= 4; off >>= 1) {
        wsum += __shfl_xor_sync(FULL, wsum, off);
        wt   += __shfl_xor_sync(FULL, wt,   off);
        wr   += __shfl_xor_sync(FULL, wr,   off);
        wg   += __shfl_xor_sync(FULL, wg,   off);
        wb   += __shfl_xor_sync(FULL, wb,   off);
    }

    // lanes 0-3 are representatives of the 4 cosets
    if (lane < 4) {
        red[wib][lane][0] = wsum;
        red[wib][lane][1] = wr;
        red[wib][lane][2] = wg;
        red[wib][lane][3] = wb;
        red[wib][lane][4] = wt;
    }
    __syncwarp();

    // lanes 0-4 each finish one output
    if (lane < 5) {
        const float* b = &red[wib][0][0];
        int vidx = (lane < 3) ? (lane + 1) : 4;   // 0->wr 1->wg 2->wb 3,4->wt
        float my = (b[0 * 6 + vidx] + b[1 * 6 + vidx])
                 + (b[2 * 6 + vidx] + b[3 * 6 + vidx]);
        float st = (b[0] + b[6]) + (b[12] + b[18]);   // total wsum (broadcast LDS)

        if (lane < 3) {
            float bg = (1.0f - st) * BG_COLOR;
            out[3 * r + lane] = my + bg;               // image r/g/b
        } else if (lane == 3) {
            out[(size_t)3 * N + r] = my;               // depth
        } else {
            out[(size_t)4 * N + r] =
                fmaxf(my - nearv, 0.0f) / (farv - nearv);  // depth_normalized
        }
    }
}

extern "C" void kernel_launch(void* const* d_in, const int* in_sizes, int n_in,
                              void* d_out, int out_size)
{
    const float* rays_o = (const float*)d_in[0];
    const float* rays_d = (const float*)d_in[1];
    const float* sigmas = (const float*)d_in[2];
    const float* rgbs   = (const float*)d_in[3];
    float* out = (float*)d_out;

    int N = in_sizes[0] / 3;   // rays_o is [N,3]

    int warps_per_block = 256 / 32;
    int blocks = (N + warps_per_block - 1) / warps_per_block;
    nerf_composite_kernel<<<blocks, 256>>>(rays_o, rays_d, sigmas, rgbs, out, N);
}